// round 5
// baseline (speedup 1.0000x reference)
#include <cuda_runtime.h>
#include <cuda_bf16.h>
#include <cstdint>
#include <math.h>

// ---------------------------------------------------------------------------
// Problem constants (fixed by reference setup_inputs)
// ---------------------------------------------------------------------------
#define N_PTS 4096
#define DIM   256
#define NTOT  8192
#define BM    128
#define NB    (NTOT / BM)            // 64 tile rows
#define NTILES (NB * (NB + 1) / 2)   // 2080 lower-triangle tiles
#define BK    64                     // K chunk (elements)
#define NCHUNK (DIM / BK)            // 4
#define SSTRIDE 144                  // padded smem row stride: 128B data + 16B pad
#define STAGE_BYTES (128 * SSTRIDE)  // 18432 per matrix per stage
#define SMEM_BUF_OFF 2048
#define SMEM_TOTAL (SMEM_BUF_OFF + 4 * STAGE_BYTES)  // 75776

// Device scratch (no allocation allowed)
__device__ __align__(16) __nv_bfloat16 g_A[NTOT * DIM];  // 4 MB bf16 copy of [X;Y]
__device__ float g_norms[NTOT];
__device__ float g_accum;
__device__ unsigned int g_ticket;

// ---------------------------------------------------------------------------
// PTX helpers (arch-neutral: sm_80+ / sm_75+)
// ---------------------------------------------------------------------------
__device__ __forceinline__ void cpasync16(uint32_t s, const void* g) {
    asm volatile("cp.async.cg.shared.global [%0], [%1], 16;" :: "r"(s), "l"(g));
}

#define LDSM_X4(R, addr) \
    asm volatile("ldmatrix.sync.aligned.m8n8.x4.shared.b16 {%0,%1,%2,%3}, [%4];" \
                 : "=r"((R)[0]), "=r"((R)[1]), "=r"((R)[2]), "=r"((R)[3]) \
                 : "r"(addr))

#define MMA16816(D, A, B) \
    asm volatile("mma.sync.aligned.m16n8k16.row.col.f32.bf16.bf16.f32 " \
                 "{%0,%1,%2,%3}, {%4,%5,%6,%7}, {%8,%9}, {%0,%1,%2,%3};" \
                 : "+f"((D)[0]), "+f"((D)[1]), "+f"((D)[2]), "+f"((D)[3]) \
                 : "r"((A)[0]), "r"((A)[1]), "r"((A)[2]), "r"((A)[3]), \
                   "r"((B)[0]), "r"((B)[1]))

// ---------------------------------------------------------------------------
// Prep: fp32->bf16 conversion + exact fp32 row norms; zero accumulators.
// One warp per row; lane handles 8 consecutive elements.
// ---------------------------------------------------------------------------
__global__ void prep_kernel(const float* __restrict__ X,
                            const float* __restrict__ Y) {
    int row  = blockIdx.x * 8 + (threadIdx.x >> 5);
    int lane = threadIdx.x & 31;
    if (blockIdx.x == 0 && threadIdx.x == 0) { g_accum = 0.0f; g_ticket = 0u; }

    const float* p = (row < N_PTS) ? (X + (size_t)row * DIM)
                                   : (Y + (size_t)(row - N_PTS) * DIM);
    float4 v0 = ((const float4*)(p + lane * 8))[0];
    float4 v1 = ((const float4*)(p + lane * 8))[1];

    float s = v0.x * v0.x + v0.y * v0.y + v0.z * v0.z + v0.w * v0.w
            + v1.x * v1.x + v1.y * v1.y + v1.z * v1.z + v1.w * v1.w;
    #pragma unroll
    for (int o = 16; o; o >>= 1) s += __shfl_xor_sync(0xffffffffu, s, o);
    if (lane == 0) g_norms[row] = s;

    __nv_bfloat162 b0 = __floats2bfloat162_rn(v0.x, v0.y);
    __nv_bfloat162 b1 = __floats2bfloat162_rn(v0.z, v0.w);
    __nv_bfloat162 b2 = __floats2bfloat162_rn(v1.x, v1.y);
    __nv_bfloat162 b3 = __floats2bfloat162_rn(v1.z, v1.w);
    uint4 packed;
    packed.x = *(uint32_t*)&b0; packed.y = *(uint32_t*)&b1;
    packed.z = *(uint32_t*)&b2; packed.w = *(uint32_t*)&b3;
    *(uint4*)(g_A + (size_t)row * DIM + lane * 8) = packed;
}

// ---------------------------------------------------------------------------
// Main mma.sync tile kernel: one 128x128 lower-triangle tile per CTA.
// 128 threads = 4 warps (2x2); warp tile 64x64; mma m16n8k16 bf16.
// Double-buffered cp.async over 4 K-chunks of 64.
// Epilogue: d^2 = ni + nj - 2g; exp only when d^2 < 40 (fp32 underflow
// elsewhere); exact diagonal added by the last CTA (atomic ticket).
// ---------------------------------------------------------------------------
__global__ __launch_bounds__(128, 2)
void mmd_mma_kernel(float* __restrict__ out) {
    extern __shared__ char smem[];
    float* srm = (float*)smem;            // 128 row norms
    float* srn = (float*)(smem + 512);    // 128 col norms
    float* red = (float*)(smem + 1024);   // 4-warp reduction
    const uint32_t sbase =
        (uint32_t)__cvta_generic_to_shared(smem + SMEM_BUF_OFF);

    // Decode lower-triangle tile index -> (bi, bj), bi >= bj
    int t  = blockIdx.x;
    int bi = (int)((sqrtf(8.0f * (float)t + 1.0f) - 1.0f) * 0.5f);
    while ((bi + 1) * (bi + 2) / 2 <= t) bi++;
    while (bi * (bi + 1) / 2 > t)        bi--;
    int bj = t - bi * (bi + 1) / 2;

    const int tid  = threadIdx.x;
    const int wid  = tid >> 5;
    const int lane = tid & 31;
    const int row0 = bi * BM;
    const int col0 = bj * BM;

    srm[tid] = g_norms[row0 + tid];
    srn[tid] = g_norms[col0 + tid];

    // cp.async issue of one K-chunk (64 elems = 128B/row) into stage st
    auto issue = [&](int c, int st) {
        uint32_t sa = sbase + st * 2 * STAGE_BYTES;
        uint32_t sb = sa + STAGE_BYTES;
        #pragma unroll
        for (int it = 0; it < 8; it++) {
            int unit = tid + it * 128;
            int r  = unit >> 3;
            int cs = unit & 7;
            uint32_t soff = r * SSTRIDE + cs * 16;
            const void* ga = g_A + (size_t)(row0 + r) * DIM + c * BK + cs * 8;
            const void* gb = g_A + (size_t)(col0 + r) * DIM + c * BK + cs * 8;
            cpasync16(sa + soff, ga);
            cpasync16(sb + soff, gb);
        }
        asm volatile("cp.async.commit_group;" ::: "memory");
    };

    float acc[4][8][4];
    #pragma unroll
    for (int mt = 0; mt < 4; mt++)
        #pragma unroll
        for (int nt = 0; nt < 8; nt++)
            #pragma unroll
            for (int r = 0; r < 4; r++) acc[mt][nt][r] = 0.0f;

    const int wm = (wid & 1) * 64;   // warp M origin
    const int wn = (wid >> 1) * 64;  // warp N origin

    issue(0, 0);

    for (int c = 0; c < NCHUNK; c++) {
        int st = c & 1;
        if (c + 1 < NCHUNK) {
            issue(c + 1, st ^ 1);
            asm volatile("cp.async.wait_group 1;" ::: "memory");
        } else {
            asm volatile("cp.async.wait_group 0;" ::: "memory");
        }
        __syncthreads();

        uint32_t sa = sbase + st * 2 * STAGE_BYTES;
        uint32_t sb = sa + STAGE_BYTES;

        #pragma unroll
        for (int s = 0; s < 4; s++) {       // 4 x k16 within the 64-chunk
            uint32_t a_frag[4][4];
            uint32_t b_frag[8][2];
            #pragma unroll
            for (int mt = 0; mt < 4; mt++) {
                uint32_t addr = sa + (wm + mt * 16 + (lane & 15)) * SSTRIDE
                              + ((lane >> 4) * 16) + s * 32;
                LDSM_X4(a_frag[mt], addr);
            }
            #pragma unroll
            for (int np = 0; np < 4; np++) {
                uint32_t R[4];
                uint32_t addr = sb + (wn + np * 16 + (lane & 15)) * SSTRIDE
                              + ((lane >> 4) * 16) + s * 32;
                LDSM_X4(R, addr);
                b_frag[np * 2 + 0][0] = R[0]; b_frag[np * 2 + 0][1] = R[2];
                b_frag[np * 2 + 1][0] = R[1]; b_frag[np * 2 + 1][1] = R[3];
            }
            #pragma unroll
            for (int mt = 0; mt < 4; mt++)
                #pragma unroll
                for (int nt = 0; nt < 8; nt++)
                    MMA16816(acc[mt][nt], a_frag[mt], b_frag[nt]);
        }
        __syncthreads();
    }

    // Epilogue
    const bool diag = (bi == bj);
    const float w = ((row0 < N_PTS) ? 1.0f : -1.0f)
                  * ((col0 < N_PTS) ? 1.0f : -1.0f)
                  * (diag ? 1.0f : 2.0f);
    float local = 0.0f;
    #pragma unroll
    for (int mt = 0; mt < 4; mt++) {
        #pragma unroll
        for (int nt = 0; nt < 8; nt++) {
            #pragma unroll
            for (int r = 0; r < 4; r++) {
                int lrow = wm + mt * 16 + (lane >> 2) + (r >> 1) * 8;
                int lcol = wn + nt * 8 + (lane & 3) * 2 + (r & 1);
                float d2 = srm[lrow] + srn[lcol] - 2.0f * acc[mt][nt][r];
                if (d2 < 40.0f) {  // everything else underflows to 0 in fp32
                    if (!(diag && lrow == lcol))
                        local += __expf(-0.5f * fmaxf(d2, 0.0f));
                }
            }
        }
    }

    #pragma unroll
    for (int o = 16; o; o >>= 1) local += __shfl_xor_sync(0xffffffffu, local, o);
    if (lane == 0) red[wid] = local;
    __syncthreads();
    if (tid == 0) {
        atomicAdd(&g_accum, w * (red[0] + red[1] + red[2] + red[3]));
        __threadfence();
        unsigned int tk = atomicAdd(&g_ticket, 1u);
        if (tk == NTILES - 1) {
            float total = *((volatile float*)&g_accum);
            out[0] = (total + (float)NTOT) * (1.0f / ((float)N_PTS * (float)N_PTS));
        }
    }
}

extern "C" void kernel_launch(void* const* d_in, const int* in_sizes, int n_in,
                              void* d_out, int out_size) {
    const float* X = (const float*)d_in[0];
    const float* Y = (const float*)d_in[1];
    float* out = (float*)d_out;

    cudaFuncSetAttribute(mmd_mma_kernel,
                         cudaFuncAttributeMaxDynamicSharedMemorySize, SMEM_TOTAL);

    prep_kernel<<<NTOT / 8, 256>>>(X, Y);
    mmd_mma_kernel<<<NTILES, 128, SMEM_TOTAL>>>(out);
}

// round 6
// speedup vs baseline: 1.2004x; 1.2004x over previous
#include <cuda_runtime.h>
#include <cuda_bf16.h>
#include <cstdint>
#include <math.h>

// ---------------------------------------------------------------------------
// Problem constants (fixed by reference setup_inputs)
// ---------------------------------------------------------------------------
#define N_PTS 4096
#define DIM   256
#define NTOT  8192
#define BM    128
#define NB    (NTOT / BM)            // 64 tile rows
#define NTILES (NB * (NB + 1) / 2)   // 2080 lower-triangle tiles
#define BK    64                     // K chunk (elements)
#define NCHUNK (DIM / BK)            // 4
#define SSTRIDE 144                  // padded smem row stride: 128B data + 16B pad
#define STAGE_BYTES (128 * SSTRIDE)  // 18432 per matrix per stage
#define SMEM_BUF_OFF 2048
#define SMEM_TOTAL (SMEM_BUF_OFF + 4 * STAGE_BYTES)  // 75776

// Device scratch (no allocation allowed)
__device__ __align__(16) __nv_bfloat16 g_A[NTOT * DIM];  // 4 MB bf16 copy of [X;Y]
__device__ float g_norms[NTOT];
__device__ float g_accum;
__device__ unsigned int g_ticket;

// ---------------------------------------------------------------------------
// PTX helpers (arch-neutral: sm_80+ / sm_75+)
// ---------------------------------------------------------------------------
__device__ __forceinline__ void cpasync16(uint32_t s, const void* g) {
    asm volatile("cp.async.cg.shared.global [%0], [%1], 16;" :: "r"(s), "l"(g));
}

#define LDSM_X4(R, addr) \
    asm volatile("ldmatrix.sync.aligned.m8n8.x4.shared.b16 {%0,%1,%2,%3}, [%4];" \
                 : "=r"((R)[0]), "=r"((R)[1]), "=r"((R)[2]), "=r"((R)[3]) \
                 : "r"(addr))

#define MMA16816(D, A, B) \
    asm volatile("mma.sync.aligned.m16n8k16.row.col.f32.bf16.bf16.f32 " \
                 "{%0,%1,%2,%3}, {%4,%5,%6,%7}, {%8,%9}, {%0,%1,%2,%3};" \
                 : "+f"((D)[0]), "+f"((D)[1]), "+f"((D)[2]), "+f"((D)[3]) \
                 : "r"((A)[0]), "r"((A)[1]), "r"((A)[2]), "r"((A)[3]), \
                   "r"((B)[0]), "r"((B)[1]))

// ---------------------------------------------------------------------------
// Prep: fp32->bf16 conversion + exact fp32 row norms; zero accumulators.
// One warp per row; lane handles 8 consecutive elements.
// ---------------------------------------------------------------------------
__global__ void prep_kernel(const float* __restrict__ X,
                            const float* __restrict__ Y) {
    int row  = blockIdx.x * 8 + (threadIdx.x >> 5);
    int lane = threadIdx.x & 31;
    if (blockIdx.x == 0 && threadIdx.x == 0) { g_accum = 0.0f; g_ticket = 0u; }

    const float* p = (row < N_PTS) ? (X + (size_t)row * DIM)
                                   : (Y + (size_t)(row - N_PTS) * DIM);
    float4 v0 = ((const float4*)(p + lane * 8))[0];
    float4 v1 = ((const float4*)(p + lane * 8))[1];

    float s = v0.x * v0.x + v0.y * v0.y + v0.z * v0.z + v0.w * v0.w
            + v1.x * v1.x + v1.y * v1.y + v1.z * v1.z + v1.w * v1.w;
    #pragma unroll
    for (int o = 16; o; o >>= 1) s += __shfl_xor_sync(0xffffffffu, s, o);
    if (lane == 0) g_norms[row] = s;

    __nv_bfloat162 b0 = __floats2bfloat162_rn(v0.x, v0.y);
    __nv_bfloat162 b1 = __floats2bfloat162_rn(v0.z, v0.w);
    __nv_bfloat162 b2 = __floats2bfloat162_rn(v1.x, v1.y);
    __nv_bfloat162 b3 = __floats2bfloat162_rn(v1.z, v1.w);
    uint4 packed;
    packed.x = *(uint32_t*)&b0; packed.y = *(uint32_t*)&b1;
    packed.z = *(uint32_t*)&b2; packed.w = *(uint32_t*)&b3;
    *(uint4*)(g_A + (size_t)row * DIM + lane * 8) = packed;
}

// ---------------------------------------------------------------------------
// Main mma.sync tile kernel: one 128x128 lower-triangle tile per CTA.
// 256 threads = 8 warps (4x2); warp tile 32x64 (round-3 shape, 4 warps/SMSP).
// Double-buffered cp.async over 4 K-chunks of 64.
// Epilogue: d^2 = ni + nj - 2g; exp only when d^2 < 40 (fp32 underflow
// elsewhere); exact diagonal added by the last CTA (atomic ticket).
// ---------------------------------------------------------------------------
__global__ __launch_bounds__(256, 2)
void mmd_mma_kernel(float* __restrict__ out) {
    extern __shared__ char smem[];
    float* srm = (float*)smem;            // 128 row norms
    float* srn = (float*)(smem + 512);    // 128 col norms
    float* red = (float*)(smem + 1024);   // 8-warp reduction
    const uint32_t sbase =
        (uint32_t)__cvta_generic_to_shared(smem + SMEM_BUF_OFF);

    // Decode lower-triangle tile index -> (bi, bj), bi >= bj
    int t  = blockIdx.x;
    int bi = (int)((sqrtf(8.0f * (float)t + 1.0f) - 1.0f) * 0.5f);
    while ((bi + 1) * (bi + 2) / 2 <= t) bi++;
    while (bi * (bi + 1) / 2 > t)        bi--;
    int bj = t - bi * (bi + 1) / 2;

    const int tid  = threadIdx.x;
    const int wid  = tid >> 5;
    const int lane = tid & 31;
    const int row0 = bi * BM;
    const int col0 = bj * BM;

    if (tid < 128) srm[tid] = g_norms[row0 + tid];
    else           srn[tid - 128] = g_norms[col0 + tid - 128];

    // cp.async issue of one K-chunk (64 elems = 128B/row) into stage st
    auto issue = [&](int c, int st) {
        uint32_t sa = sbase + st * 2 * STAGE_BYTES;
        uint32_t sb = sa + STAGE_BYTES;
        #pragma unroll
        for (int it = 0; it < 4; it++) {
            int unit = tid + it * 256;
            int r  = unit >> 3;
            int cs = unit & 7;
            uint32_t soff = r * SSTRIDE + cs * 16;
            const void* ga = g_A + (size_t)(row0 + r) * DIM + c * BK + cs * 8;
            const void* gb = g_A + (size_t)(col0 + r) * DIM + c * BK + cs * 8;
            cpasync16(sa + soff, ga);
            cpasync16(sb + soff, gb);
        }
        asm volatile("cp.async.commit_group;" ::: "memory");
    };

    float acc[2][8][4];
    #pragma unroll
    for (int mt = 0; mt < 2; mt++)
        #pragma unroll
        for (int nt = 0; nt < 8; nt++)
            #pragma unroll
            for (int r = 0; r < 4; r++) acc[mt][nt][r] = 0.0f;

    const int wm = (wid & 3) * 32;   // warp M origin
    const int wn = (wid >> 2) * 64;  // warp N origin

    // Hoisted per-thread ldmatrix base offsets (stage-relative)
    const uint32_t a_base = (wm + (lane & 15)) * SSTRIDE + ((lane >> 4) * 16);
    const uint32_t b_base = (wn + (lane & 15)) * SSTRIDE + ((lane >> 4) * 16);

    issue(0, 0);

    for (int c = 0; c < NCHUNK; c++) {
        int st = c & 1;
        if (c + 1 < NCHUNK) {
            issue(c + 1, st ^ 1);
            asm volatile("cp.async.wait_group 1;" ::: "memory");
        } else {
            asm volatile("cp.async.wait_group 0;" ::: "memory");
        }
        __syncthreads();

        uint32_t sa = sbase + st * 2 * STAGE_BYTES;
        uint32_t sb = sa + STAGE_BYTES;

        #pragma unroll
        for (int s = 0; s < 4; s++) {       // 4 x k16 within the 64-chunk
            uint32_t a_frag[2][4];
            uint32_t b_frag[8][2];
            #pragma unroll
            for (int mt = 0; mt < 2; mt++)
                LDSM_X4(a_frag[mt], sa + a_base + mt * (16 * SSTRIDE) + s * 32);
            #pragma unroll
            for (int np = 0; np < 4; np++) {
                uint32_t R[4];
                LDSM_X4(R, sb + b_base + np * (16 * SSTRIDE) + s * 32);
                b_frag[np * 2 + 0][0] = R[0]; b_frag[np * 2 + 0][1] = R[2];
                b_frag[np * 2 + 1][0] = R[1]; b_frag[np * 2 + 1][1] = R[3];
            }
            #pragma unroll
            for (int mt = 0; mt < 2; mt++)
                #pragma unroll
                for (int nt = 0; nt < 8; nt++)
                    MMA16816(acc[mt][nt], a_frag[mt], b_frag[nt]);
        }
        __syncthreads();
    }

    // Epilogue
    const bool diag = (bi == bj);
    const float w = ((row0 < N_PTS) ? 1.0f : -1.0f)
                  * ((col0 < N_PTS) ? 1.0f : -1.0f)
                  * (diag ? 1.0f : 2.0f);
    float local = 0.0f;
    #pragma unroll
    for (int mt = 0; mt < 2; mt++) {
        #pragma unroll
        for (int nt = 0; nt < 8; nt++) {
            #pragma unroll
            for (int r = 0; r < 4; r++) {
                int lrow = wm + mt * 16 + (lane >> 2) + (r >> 1) * 8;
                int lcol = wn + nt * 8 + (lane & 3) * 2 + (r & 1);
                float d2 = srm[lrow] + srn[lcol] - 2.0f * acc[mt][nt][r];
                if (d2 < 40.0f) {  // everything else underflows to 0 in fp32
                    if (!(diag && lrow == lcol))
                        local += __expf(-0.5f * fmaxf(d2, 0.0f));
                }
            }
        }
    }

    #pragma unroll
    for (int o = 16; o; o >>= 1) local += __shfl_xor_sync(0xffffffffu, local, o);
    if (lane == 0) red[wid] = local;
    __syncthreads();
    if (tid == 0) {
        float v = 0.0f;
        #pragma unroll
        for (int i = 0; i < 8; i++) v += red[i];
        atomicAdd(&g_accum, w * v);
        __threadfence();
        unsigned int tk = atomicAdd(&g_ticket, 1u);
        if (tk == NTILES - 1) {
            float total = *((volatile float*)&g_accum);
            out[0] = (total + (float)NTOT) * (1.0f / ((float)N_PTS * (float)N_PTS));
        }
    }
}

extern "C" void kernel_launch(void* const* d_in, const int* in_sizes, int n_in,
                              void* d_out, int out_size) {
    const float* X = (const float*)d_in[0];
    const float* Y = (const float*)d_in[1];
    float* out = (float*)d_out;

    cudaFuncSetAttribute(mmd_mma_kernel,
                         cudaFuncAttributeMaxDynamicSharedMemorySize, SMEM_TOTAL);

    prep_kernel<<<NTOT / 8, 256>>>(X, Y);
    mmd_mma_kernel<<<NTILES, 256, SMEM_TOTAL>>>(out);
}